// round 9
// baseline (speedup 1.0000x reference)
#include <cuda_runtime.h>
#include <cuda_fp16.h>
#include <cstdint>

// Problem constants
#define N_NODES 100000
#define N_EDGES 400000
#define DIM     128
#define KDIM    384       // 3*DIM
#define HID     768       // 6*DIM
#define TILE_M  128
#define N_TILES (N_EDGES / TILE_M)   // 3125
#define N_STEPS 8                    // 768 / 96 n-cols per step
#define KTILES  24                   // 384 / 16
#define NTPS    12                   // n-tiles per step (96/8)

// W1 in fp16, m16n8k16 B-fragment order:
// [step 8][ntile 12][ktile 24][lane 32][2 x b32]  (72 KB per step)
__device__ __align__(16) __half g_w1frag[HID * KDIM];

static constexpr uint32_t B_STEP_BYTES = NTPS * KTILES * 32 * 8;  // 73728

// ---------------- SMEM layout ----------------
// A (feat fragments): [mtile 8][ktile 24][lane 32][4 x b32] = 98304
static constexpr int SM_A    = 0;
static constexpr int SM_B    = 98304;    // single 73728 buffer (reg-staged prefetch)
static constexpr int SM_W2   = 172032;   // 768 f32
static constexpr int SM_B1   = 175104;   // 768 f32
static constexpr int SM_PART = 178176;   // 3 x 128 f32
static constexpr int SMEM_TOTAL = 179712;

// ---------------- helpers ----------------
__device__ __forceinline__ void mma16816(float* d, const uint32_t* a, const uint32_t* b) {
    asm volatile(
        "mma.sync.aligned.m16n8k16.row.col.f32.f16.f16.f32 "
        "{%0,%1,%2,%3}, {%4,%5,%6,%7}, {%8,%9}, {%0,%1,%2,%3};"
        : "+f"(d[0]), "+f"(d[1]), "+f"(d[2]), "+f"(d[3])
        : "r"(a[0]), "r"(a[1]), "r"(a[2]), "r"(a[3]), "r"(b[0]), "r"(b[1]));
}

// A-fragment smem byte offset for (row r in 0..127, kpair p in 0..191)
__device__ __forceinline__ uint32_t a_frag_off(int r, int p) {
    int kt   = p >> 3;
    int kp   = p & 7;
    int ln   = ((r & 7) << 2) + (kp & 3);
    int word = ((r >> 3) & 1) + ((kp >> 2) << 1);
    int mt   = r >> 4;
    return (uint32_t)(((mt * KTILES + kt) << 9) + (ln << 4) + (word << 2));
}

// ---------------- prep: W1 fp32 -> fp16 fragment-ordered ----------------
__global__ void prep_w1_kernel(const float* __restrict__ W1) {
    int i = blockIdx.x * blockDim.x + threadIdx.x;
    if (i >= HID * KDIM) return;
    int n = i / KDIM;
    int k = i - n * KDIM;
    int step = n / 96;
    int np   = n - step * 96;
    int nt   = np >> 3;
    int g    = np & 7;
    int kt   = k >> 4;
    int kk   = k & 15;
    int w    = kk >> 3;
    int t    = (kk & 7) >> 1;
    int half = kk & 1;
    uint32_t off = (uint32_t)step * B_STEP_BYTES
                 + (uint32_t)((nt * KTILES + kt) << 8)
                 + (uint32_t)(((g << 2) + t) << 3) + (uint32_t)(w << 2) + (uint32_t)(half << 1);
    *(__half*)((char*)g_w1frag + off) = __float2half_rn(W1[i]);
}

// ---------------- main fused kernel ----------------
__global__ void __launch_bounds__(384) edge_mlp_hmma(
    const float* __restrict__ x,
    const int* __restrict__ ei,     // int32 (JAX x64 disabled)
    const float* __restrict__ b1g,
    const float* __restrict__ w2g,
    const float* __restrict__ b2g,
    float* __restrict__ out)
{
    extern __shared__ char smem[];
    const int tid  = threadIdx.x;
    const int lane = tid & 31;
    const int wid  = tid >> 5;
    const int mg   = wid & 3;      // 4 m-groups (32 rows each)
    const int ng   = wid >> 2;     // 3 n-groups (32 cols per step each)
    const int e0   = blockIdx.x * TILE_M;

    // ---- register-staged prefetch of B step 0 (L2-hot) ----
    uint4 R[12];
    {
        const char* s = (const char*)g_w1frag + (uint32_t)tid * 16u;
#pragma unroll
        for (int j = 0; j < 12; j++)
            R[j] = *(const uint4*)(s + j * 6144);
    }

    // Stage w2 / b1 into smem
    float* w2s = (float*)(smem + SM_W2);
    float* b1s = (float*)(smem + SM_B1);
    { int i0 = tid, i1 = tid + 384;
      w2s[i0] = w2g[i0]; w2s[i1] = w2g[i1];
      b1s[i0] = b1g[i0]; b1s[i1] = b1g[i1]; }

    // ---- build feat tile into smem A-fragment layout (threads 0..255) ----
    // Section kpair bases: mean 0, prod 64, sqdiff 128.
    if (tid < 256) {
        const int r  = tid & 127;
        const int qb = (tid >> 7) * 16;
        const int i0 = ei[e0 + r];
        const int i1 = ei[N_EDGES + e0 + r];
        const float4* p0 = (const float4*)x + (size_t)i0 * 32 + qb;
        const float4* p1 = (const float4*)x + (size_t)i1 * 32 + qb;
        char* As = smem + SM_A;
#pragma unroll 4
        for (int q = 0; q < 16; q++) {
            float4 a = p0[q];
            float4 c = p1[q];
            int qg = qb + q;
            __half2 h;
            h = __floats2half2_rn((a.x + c.x) * 0.5f, (a.y + c.y) * 0.5f);
            *(uint32_t*)(As + a_frag_off(r, 2 * qg))          = *(uint32_t*)&h;
            h = __floats2half2_rn((a.z + c.z) * 0.5f, (a.w + c.w) * 0.5f);
            *(uint32_t*)(As + a_frag_off(r, 2 * qg + 1))      = *(uint32_t*)&h;
            h = __floats2half2_rn(a.x * c.x, a.y * c.y);
            *(uint32_t*)(As + a_frag_off(r, 64 + 2 * qg))     = *(uint32_t*)&h;
            h = __floats2half2_rn(a.z * c.z, a.w * c.w);
            *(uint32_t*)(As + a_frag_off(r, 64 + 2 * qg + 1)) = *(uint32_t*)&h;
            float d0 = a.x - c.x, d1 = a.y - c.y, d2 = a.z - c.z, d3 = a.w - c.w;
            h = __floats2half2_rn(d0 * d0, d1 * d1);
            *(uint32_t*)(As + a_frag_off(r, 128 + 2 * qg))     = *(uint32_t*)&h;
            h = __floats2half2_rn(d2 * d2, d3 * d3);
            *(uint32_t*)(As + a_frag_off(r, 128 + 2 * qg + 1)) = *(uint32_t*)&h;
        }
    }

    // Store staged B step 0 into smem
    {
        char* Bd = smem + SM_B + (uint32_t)tid * 16u;
#pragma unroll
        for (int j = 0; j < 12; j++)
            *(uint4*)(Bd + j * 6144) = R[j];
    }
    __syncthreads();   // A + B(step0) + w2/b1 ready

    // 4 per-lane row accumulators: [mt0 g, mt0 g+8, mt1 g, mt1 g+8]
    float accv[4] = {0.f, 0.f, 0.f, 0.f};
    const int t4 = lane & 3;

    const uint32_t a_off0 = (uint32_t)SM_A + (uint32_t)(mg * 2 * KTILES) * 512u + (uint32_t)lane * 16u;
    const uint32_t b_off0 = (uint32_t)SM_B + (uint32_t)(ng * 4 * KTILES) * 256u + (uint32_t)lane * 8u;

#pragma unroll 1
    for (int s = 0; s < N_STEPS; s++) {
        // prefetch step s+1 into registers (hidden under the MMA loop)
        if (s + 1 < N_STEPS) {
            const char* src = (const char*)g_w1frag
                            + (uint32_t)(s + 1) * B_STEP_BYTES + (uint32_t)tid * 16u;
#pragma unroll
            for (int j = 0; j < 12; j++)
                R[j] = *(const uint4*)(src + j * 6144);
        }

        float C[8][4];
#pragma unroll
        for (int f = 0; f < 8; f++)
#pragma unroll
            for (int v = 0; v < 4; v++) C[f][v] = 0.f;

#pragma unroll
        for (int kt = 0; kt < KTILES; kt++) {
            uint4 A0 = *(const uint4*)(smem + a_off0 + (uint32_t)kt * 512u);
            uint4 A1 = *(const uint4*)(smem + a_off0 + (uint32_t)(KTILES * 512) + (uint32_t)kt * 512u);
            uint2 B0 = *(const uint2*)(smem + b_off0 + (uint32_t)(0 * KTILES + kt) * 256u);
            uint2 B1 = *(const uint2*)(smem + b_off0 + (uint32_t)(1 * KTILES + kt) * 256u);
            uint2 B2 = *(const uint2*)(smem + b_off0 + (uint32_t)(2 * KTILES + kt) * 256u);
            uint2 B3 = *(const uint2*)(smem + b_off0 + (uint32_t)(3 * KTILES + kt) * 256u);
            mma16816(C[0], (const uint32_t*)&A0, (const uint32_t*)&B0);
            mma16816(C[1], (const uint32_t*)&A0, (const uint32_t*)&B1);
            mma16816(C[2], (const uint32_t*)&A0, (const uint32_t*)&B2);
            mma16816(C[3], (const uint32_t*)&A0, (const uint32_t*)&B3);
            mma16816(C[4], (const uint32_t*)&A1, (const uint32_t*)&B0);
            mma16816(C[5], (const uint32_t*)&A1, (const uint32_t*)&B1);
            mma16816(C[6], (const uint32_t*)&A1, (const uint32_t*)&B2);
            mma16816(C[7], (const uint32_t*)&A1, (const uint32_t*)&B3);
        }

        // fold relu(. + b1) * w2 into per-row accumulators
        const int nb = s * 96 + ng * 32 + t4 * 2;
#pragma unroll
        for (int nt = 0; nt < 4; nt++) {
            const int c0 = nb + nt * 8;
            float2 bb = *(const float2*)&b1s[c0];
            float2 ww = *(const float2*)&w2s[c0];
#pragma unroll
            for (int mt = 0; mt < 2; mt++) {
                float* d = C[mt * 4 + nt];
                accv[mt * 2 + 0] += fmaxf(d[0] + bb.x, 0.f) * ww.x
                                 + fmaxf(d[1] + bb.y, 0.f) * ww.y;
                accv[mt * 2 + 1] += fmaxf(d[2] + bb.x, 0.f) * ww.x
                                 + fmaxf(d[3] + bb.y, 0.f) * ww.y;
            }
        }

        __syncthreads();   // all warps done reading B step s
        if (s + 1 < N_STEPS) {
            char* Bd = smem + SM_B + (uint32_t)tid * 16u;
#pragma unroll
            for (int j = 0; j < 12; j++)
                *(uint4*)(Bd + j * 6144) = R[j];
            __syncthreads();   // B step s+1 ready
        }
    }

    // reduce the 4 lanes sharing a g-group
#pragma unroll
    for (int i = 0; i < 4; i++) {
        accv[i] += __shfl_xor_sync(0xffffffffu, accv[i], 1);
        accv[i] += __shfl_xor_sync(0xffffffffu, accv[i], 2);
    }

    float* part = (float*)(smem + SM_PART);
    if (t4 == 0) {
        const int g = lane >> 2;
        const int rb = mg * 32;
        part[ng * 128 + rb + g]      = accv[0];
        part[ng * 128 + rb + 8 + g]  = accv[1];
        part[ng * 128 + rb + 16 + g] = accv[2];
        part[ng * 128 + rb + 24 + g] = accv[3];
    }
    __syncthreads();
    if (tid < 128)
        out[e0 + tid] = part[tid] + part[128 + tid] + part[256 + tid] + b2g[0];
}

// ---------------- launch ----------------
extern "C" void kernel_launch(void* const* d_in, const int* in_sizes, int n_in,
                              void* d_out, int out_size) {
    const float* x  = (const float*)d_in[0];
    const int*   ei = (const int*)d_in[1];   // int32 (JAX default: x64 disabled)
    // d_in[2] edge_attr3, d_in[3] edge_attr4, d_in[4] batch: unused by reference
    const float* W1 = (const float*)d_in[5];
    const float* b1 = (const float*)d_in[6];
    const float* W2 = (const float*)d_in[7];
    const float* b2 = (const float*)d_in[8];
    float* out = (float*)d_out;

    prep_w1_kernel<<<(HID * KDIM + 255) / 256, 256>>>(W1);

    cudaFuncSetAttribute(edge_mlp_hmma,
                         cudaFuncAttributeMaxDynamicSharedMemorySize, SMEM_TOTAL);
    edge_mlp_hmma<<<N_TILES, 384, SMEM_TOTAL>>>(x, ei, b1, W2, b2, out);
}

// round 10
// speedup vs baseline: 1.0908x; 1.0908x over previous
#include <cuda_runtime.h>
#include <cuda_fp16.h>
#include <cstdint>

// Problem constants
#define N_NODES 100000
#define N_EDGES 400000
#define DIM     128
#define KDIM    384       // 3*DIM
#define HID     768       // 6*DIM
#define TILE_M  128
#define N_TILES (N_EDGES / TILE_M)   // 3125
#define N_STEPS 6                    // 768 / 128 n-cols per step
#define KTILES  24                   // 384 / 16

// W1 fp16, m16n8k16 B-fragment order, grouped for half-step cp.async:
// [step 6][khalf 2][ntile 16][ktile12][lane 32][8B]   (96 KB per step, 48 KB per half)
__device__ __align__(16) __half g_w1frag[HID * KDIM];

static constexpr uint32_t B_STEP_BYTES = 16 * 24 * 32 * 8;   // 98304
static constexpr uint32_t B_HALF_BYTES = B_STEP_BYTES / 2;   // 49152

// ---------------- SMEM layout ----------------
// A (feat fragments): [mtile 8][ktile 24][lane 32][16B] = 98304
static constexpr int SM_A    = 0;
static constexpr int SM_BH0  = 98304;    // B half-buffer 0 (kt 0..11)
static constexpr int SM_BH1  = 147456;   // B half-buffer 1 (kt 12..23)
static constexpr int SM_W2   = 196608;   // 768 f32
static constexpr int SM_B1   = 199680;   // 768 f32
static constexpr int SM_PART = 202752;   // 4 x 128 f32
static constexpr int SMEM_TOTAL = 204800;

// ---------------- helpers ----------------
__device__ __forceinline__ uint32_t smem_u32(const void* p) {
    uint32_t a;
    asm("{ .reg .u64 t; cvta.to.shared.u64 t, %1; cvt.u32.u64 %0, t; }" : "=r"(a) : "l"(p));
    return a;
}
__device__ __forceinline__ void cp16(uint32_t dst, const void* src) {
    asm volatile("cp.async.cg.shared.global [%0], [%1], 16;" :: "r"(dst), "l"(src) : "memory");
}
__device__ __forceinline__ void cp_commit() {
    asm volatile("cp.async.commit_group;" ::: "memory");
}
template <int N>
__device__ __forceinline__ void cp_wait() {
    asm volatile("cp.async.wait_group %0;" :: "n"(N) : "memory");
}
__device__ __forceinline__ void mma16816(float* d, const uint32_t* a, const uint32_t* b) {
    asm volatile(
        "mma.sync.aligned.m16n8k16.row.col.f32.f16.f16.f32 "
        "{%0,%1,%2,%3}, {%4,%5,%6,%7}, {%8,%9}, {%0,%1,%2,%3};"
        : "+f"(d[0]), "+f"(d[1]), "+f"(d[2]), "+f"(d[3])
        : "r"(a[0]), "r"(a[1]), "r"(a[2]), "r"(a[3]), "r"(b[0]), "r"(b[1]));
}

// A-fragment smem byte offset for (row r in 0..127, kpair p in 0..191)
__device__ __forceinline__ uint32_t a_frag_off(int r, int p) {
    int kt   = p >> 3;
    int kp   = p & 7;
    int ln   = ((r & 7) << 2) + (kp & 3);
    int word = ((r >> 3) & 1) + ((kp >> 2) << 1);
    int mt   = r >> 4;
    return (uint32_t)(((mt * KTILES + kt) << 9) + (ln << 4) + (word << 2));
}

// ---------------- prep: W1 fp32 -> fp16 fragment-ordered ----------------
__global__ void prep_w1_kernel(const float* __restrict__ W1) {
    int i = blockIdx.x * blockDim.x + threadIdx.x;
    if (i >= HID * KDIM) return;
    int n = i / KDIM;
    int k = i - n * KDIM;
    int step = n >> 7;            // 128 cols per step
    int np   = n & 127;
    int nt   = np >> 3;           // 16 ntiles per step
    int g    = np & 7;
    int kt   = k >> 4;
    int half = (kt >= 12) ? 1 : 0;
    int kt12 = kt - half * 12;
    int kk   = k & 15;
    int w    = kk >> 3;
    int t    = (kk & 7) >> 1;
    int hb   = kk & 1;
    uint32_t off = (uint32_t)step * B_STEP_BYTES + (uint32_t)half * B_HALF_BYTES
                 + (uint32_t)((nt * 12 + kt12) << 8)
                 + (uint32_t)(((g << 2) + t) << 3) + (uint32_t)(w << 2) + (uint32_t)(hb << 1);
    *(__half*)((char*)g_w1frag + off) = __float2half_rn(W1[i]);
}

// ---------------- main fused kernel ----------------
__global__ void __launch_bounds__(256, 1) edge_mlp_hmma(
    const float* __restrict__ x,
    const int* __restrict__ ei,     // int32 (JAX x64 disabled)
    const float* __restrict__ b1g,
    const float* __restrict__ w2g,
    const float* __restrict__ b2g,
    float* __restrict__ out)
{
    extern __shared__ char smem[];
    const uint32_t sb = smem_u32(smem);
    const int tid  = threadIdx.x;
    const int lane = tid & 31;
    const int wid  = tid >> 5;
    const int mg   = wid & 1;      // 2 m-groups (64 rows each = 4 mtiles)
    const int ng   = wid >> 1;     // 4 n-groups (32 cols per step each = 4 ntiles)
    const int e0   = blockIdx.x * TILE_M;

    // prologue: cp.async step0 half0 + half1 (two commit groups)
    {
        const char* g0 = (const char*)g_w1frag + (uint32_t)tid * 16u;
#pragma unroll
        for (int j = 0; j < 12; j++)
            cp16(sb + SM_BH0 + tid * 16 + j * 4096, g0 + j * 4096);
        cp_commit();
#pragma unroll
        for (int j = 0; j < 12; j++)
            cp16(sb + SM_BH1 + tid * 16 + j * 4096, g0 + B_HALF_BYTES + j * 4096);
        cp_commit();
    }

    // stage w2 / b1
    float* w2s = (float*)(smem + SM_W2);
    float* b1s = (float*)(smem + SM_B1);
#pragma unroll
    for (int i = 0; i < 3; i++) { w2s[tid + i * 256] = w2g[tid + i * 256];
                                  b1s[tid + i * 256] = b1g[tid + i * 256]; }

    // ---- build feat tile into smem A-fragment layout ----
    // Section kpair bases: mean 0, prod 64, sqdiff 128.
    {
        const int r  = tid & 127;
        const int qb = (tid >> 7) * 16;
        const int i0 = ei[e0 + r];
        const int i1 = ei[N_EDGES + e0 + r];
        const float4* p0 = (const float4*)x + (size_t)i0 * 32 + qb;
        const float4* p1 = (const float4*)x + (size_t)i1 * 32 + qb;
        char* As = smem + SM_A;
#pragma unroll 4
        for (int q = 0; q < 16; q++) {
            float4 a = p0[q];
            float4 c = p1[q];
            int qg = qb + q;
            __half2 h;
            h = __floats2half2_rn((a.x + c.x) * 0.5f, (a.y + c.y) * 0.5f);
            *(uint32_t*)(As + a_frag_off(r, 2 * qg))          = *(uint32_t*)&h;
            h = __floats2half2_rn((a.z + c.z) * 0.5f, (a.w + c.w) * 0.5f);
            *(uint32_t*)(As + a_frag_off(r, 2 * qg + 1))      = *(uint32_t*)&h;
            h = __floats2half2_rn(a.x * c.x, a.y * c.y);
            *(uint32_t*)(As + a_frag_off(r, 64 + 2 * qg))     = *(uint32_t*)&h;
            h = __floats2half2_rn(a.z * c.z, a.w * c.w);
            *(uint32_t*)(As + a_frag_off(r, 64 + 2 * qg + 1)) = *(uint32_t*)&h;
            float d0 = a.x - c.x, d1 = a.y - c.y, d2 = a.z - c.z, d3 = a.w - c.w;
            h = __floats2half2_rn(d0 * d0, d1 * d1);
            *(uint32_t*)(As + a_frag_off(r, 128 + 2 * qg))     = *(uint32_t*)&h;
            h = __floats2half2_rn(d2 * d2, d3 * d3);
            *(uint32_t*)(As + a_frag_off(r, 128 + 2 * qg + 1)) = *(uint32_t*)&h;
        }
    }

    // 8 per-lane row accumulators: [mt 0..3][rowhalf 0..1]
    float accv[8];
#pragma unroll
    for (int i = 0; i < 8; i++) accv[i] = 0.f;
    const int t4 = lane & 3;

    const uint32_t a_base = (uint32_t)SM_A + (uint32_t)(mg * 4 * KTILES) * 512u + (uint32_t)lane * 16u;
    const uint32_t b_rel  = (uint32_t)(ng * 4 * 12) * 256u + (uint32_t)lane * 8u;

#pragma unroll 1
    for (int s = 0; s < N_STEPS; s++) {
        float C[16][4];
#pragma unroll
        for (int f = 0; f < 16; f++)
#pragma unroll
            for (int v = 0; v < 4; v++) C[f][v] = 0.f;

        // ---------- half 0 (kt 0..11) ----------
        cp_wait<1>();          // H0(s) complete (H1(s) may be pending)
        __syncthreads();       // also orders A-build on s==0
#pragma unroll
        for (int kt = 0; kt < 12; kt++) {
            uint4 A0 = *(const uint4*)(smem + a_base + (uint32_t)(0 * KTILES + kt) * 512u);
            uint4 A1 = *(const uint4*)(smem + a_base + (uint32_t)(1 * KTILES + kt) * 512u);
            uint4 A2 = *(const uint4*)(smem + a_base + (uint32_t)(2 * KTILES + kt) * 512u);
            uint4 A3 = *(const uint4*)(smem + a_base + (uint32_t)(3 * KTILES + kt) * 512u);
            uint2 B0 = *(const uint2*)(smem + SM_BH0 + b_rel + (uint32_t)(0 * 12 + kt) * 256u);
            uint2 B1 = *(const uint2*)(smem + SM_BH0 + b_rel + (uint32_t)(1 * 12 + kt) * 256u);
            uint2 B2 = *(const uint2*)(smem + SM_BH0 + b_rel + (uint32_t)(2 * 12 + kt) * 256u);
            uint2 B3 = *(const uint2*)(smem + SM_BH0 + b_rel + (uint32_t)(3 * 12 + kt) * 256u);
            mma16816(C[0],  (const uint32_t*)&A0, (const uint32_t*)&B0);
            mma16816(C[1],  (const uint32_t*)&A0, (const uint32_t*)&B1);
            mma16816(C[2],  (const uint32_t*)&A0, (const uint32_t*)&B2);
            mma16816(C[3],  (const uint32_t*)&A0, (const uint32_t*)&B3);
            mma16816(C[4],  (const uint32_t*)&A1, (const uint32_t*)&B0);
            mma16816(C[5],  (const uint32_t*)&A1, (const uint32_t*)&B1);
            mma16816(C[6],  (const uint32_t*)&A1, (const uint32_t*)&B2);
            mma16816(C[7],  (const uint32_t*)&A1, (const uint32_t*)&B3);
            mma16816(C[8],  (const uint32_t*)&A2, (const uint32_t*)&B0);
            mma16816(C[9],  (const uint32_t*)&A2, (const uint32_t*)&B1);
            mma16816(C[10], (const uint32_t*)&A2, (const uint32_t*)&B2);
            mma16816(C[11], (const uint32_t*)&A2, (const uint32_t*)&B3);
            mma16816(C[12], (const uint32_t*)&A3, (const uint32_t*)&B0);
            mma16816(C[13], (const uint32_t*)&A3, (const uint32_t*)&B1);
            mma16816(C[14], (const uint32_t*)&A3, (const uint32_t*)&B2);
            mma16816(C[15], (const uint32_t*)&A3, (const uint32_t*)&B3);
        }
        __syncthreads();       // all warps done with BH0
        if (s + 1 < N_STEPS) { // refill BH0 with next step's half0
            const char* g0 = (const char*)g_w1frag
                           + (uint32_t)(s + 1) * B_STEP_BYTES + (uint32_t)tid * 16u;
#pragma unroll
            for (int j = 0; j < 12; j++)
                cp16(sb + SM_BH0 + tid * 16 + j * 4096, g0 + j * 4096);
            cp_commit();
            cp_wait<1>();      // H1(s) complete (H0(s+1) pending)
        } else {
            cp_wait<0>();      // H1(s) complete
        }
        __syncthreads();

        // ---------- half 1 (kt 12..23) ----------
#pragma unroll
        for (int kt = 0; kt < 12; kt++) {
            uint4 A0 = *(const uint4*)(smem + a_base + (uint32_t)(0 * KTILES + 12 + kt) * 512u);
            uint4 A1 = *(const uint4*)(smem + a_base + (uint32_t)(1 * KTILES + 12 + kt) * 512u);
            uint4 A2 = *(const uint4*)(smem + a_base + (uint32_t)(2 * KTILES + 12 + kt) * 512u);
            uint4 A3 = *(const uint4*)(smem + a_base + (uint32_t)(3 * KTILES + 12 + kt) * 512u);
            uint2 B0 = *(const uint2*)(smem + SM_BH1 + b_rel + (uint32_t)(0 * 12 + kt) * 256u);
            uint2 B1 = *(const uint2*)(smem + SM_BH1 + b_rel + (uint32_t)(1 * 12 + kt) * 256u);
            uint2 B2 = *(const uint2*)(smem + SM_BH1 + b_rel + (uint32_t)(2 * 12 + kt) * 256u);
            uint2 B3 = *(const uint2*)(smem + SM_BH1 + b_rel + (uint32_t)(3 * 12 + kt) * 256u);
            mma16816(C[0],  (const uint32_t*)&A0, (const uint32_t*)&B0);
            mma16816(C[1],  (const uint32_t*)&A0, (const uint32_t*)&B1);
            mma16816(C[2],  (const uint32_t*)&A0, (const uint32_t*)&B2);
            mma16816(C[3],  (const uint32_t*)&A0, (const uint32_t*)&B3);
            mma16816(C[4],  (const uint32_t*)&A1, (const uint32_t*)&B0);
            mma16816(C[5],  (const uint32_t*)&A1, (const uint32_t*)&B1);
            mma16816(C[6],  (const uint32_t*)&A1, (const uint32_t*)&B2);
            mma16816(C[7],  (const uint32_t*)&A1, (const uint32_t*)&B3);
            mma16816(C[8],  (const uint32_t*)&A2, (const uint32_t*)&B0);
            mma16816(C[9],  (const uint32_t*)&A2, (const uint32_t*)&B1);
            mma16816(C[10], (const uint32_t*)&A2, (const uint32_t*)&B2);
            mma16816(C[11], (const uint32_t*)&A2, (const uint32_t*)&B3);
            mma16816(C[12], (const uint32_t*)&A3, (const uint32_t*)&B0);
            mma16816(C[13], (const uint32_t*)&A3, (const uint32_t*)&B1);
            mma16816(C[14], (const uint32_t*)&A3, (const uint32_t*)&B2);
            mma16816(C[15], (const uint32_t*)&A3, (const uint32_t*)&B3);
        }
        __syncthreads();       // all warps done with BH1
        if (s + 1 < N_STEPS) { // refill BH1 with next step's half1
            const char* g1 = (const char*)g_w1frag
                           + (uint32_t)(s + 1) * B_STEP_BYTES + B_HALF_BYTES + (uint32_t)tid * 16u;
#pragma unroll
            for (int j = 0; j < 12; j++)
                cp16(sb + SM_BH1 + tid * 16 + j * 4096, g1 + j * 4096);
            cp_commit();
        }

        // ---------- fold relu(. + b1) * w2 ----------
        const int nb = s * 128 + ng * 32 + t4 * 2;
#pragma unroll
        for (int bt = 0; bt < 4; bt++) {
            const int c0 = nb + bt * 8;
            float2 bb = *(const float2*)&b1s[c0];
            float2 ww = *(const float2*)&w2s[c0];
#pragma unroll
            for (int mt = 0; mt < 4; mt++) {
                float* d = C[mt * 4 + bt];
                accv[mt * 2 + 0] += fmaxf(d[0] + bb.x, 0.f) * ww.x
                                 + fmaxf(d[1] + bb.y, 0.f) * ww.y;
                accv[mt * 2 + 1] += fmaxf(d[2] + bb.x, 0.f) * ww.x
                                 + fmaxf(d[3] + bb.y, 0.f) * ww.y;
            }
        }
    }

    // reduce the 4 lanes sharing a g-group
#pragma unroll
    for (int i = 0; i < 8; i++) {
        accv[i] += __shfl_xor_sync(0xffffffffu, accv[i], 1);
        accv[i] += __shfl_xor_sync(0xffffffffu, accv[i], 2);
    }

    float* part = (float*)(smem + SM_PART);
    if (t4 == 0) {
        const int g = lane >> 2;
#pragma unroll
        for (int mt = 0; mt < 4; mt++) {
            const int row = mg * 64 + mt * 16 + g;
            part[ng * 128 + row]     = accv[mt * 2 + 0];
            part[ng * 128 + row + 8] = accv[mt * 2 + 1];
        }
    }
    __syncthreads();
    if (tid < 128)
        out[e0 + tid] = part[tid] + part[128 + tid] + part[256 + tid] + part[384 + tid] + b2g[0];
}

// ---------------- launch ----------------
extern "C" void kernel_launch(void* const* d_in, const int* in_sizes, int n_in,
                              void* d_out, int out_size) {
    const float* x  = (const float*)d_in[0];
    const int*   ei = (const int*)d_in[1];   // int32 (JAX default: x64 disabled)
    // d_in[2] edge_attr3, d_in[3] edge_attr4, d_in[4] batch: unused by reference
    const float* W1 = (const float*)d_in[5];
    const float* b1 = (const float*)d_in[6];
    const float* W2 = (const float*)d_in[7];
    const float* b2 = (const float*)d_in[8];
    float* out = (float*)d_out;

    prep_w1_kernel<<<(HID * KDIM + 255) / 256, 256>>>(W1);

    cudaFuncSetAttribute(edge_mlp_hmma,
                         cudaFuncAttributeMaxDynamicSharedMemorySize, SMEM_TOTAL);
    edge_mlp_hmma<<<N_TILES, 256, SMEM_TOTAL>>>(x, ei, b1, W2, b2, out);
}